// round 3
// baseline (speedup 1.0000x reference)
#include <cuda_runtime.h>

#define NN 100000
#define NE 1600000

// ---------------- device scratch (static allocation, allowed) ----------------
__device__ int   g_deg_in[NN];
__device__ int   g_deg_out[NN];
__device__ int   g_cursor[NN];
__device__ float g_norm_src[NN];
__device__ float g_norm_dst[NN];
__device__ int   g_row_ptr[NN + 1];
__device__ int   g_csr_src[NE];
__device__ float g_agg1[(size_t)NN * 128];
__device__ float g_h1[(size_t)NN * 128];
__device__ float g_t[(size_t)NN * 64];

// ---------------- small setup kernels ----------------
__global__ void k_zero(int n) {
    int i = blockIdx.x * blockDim.x + threadIdx.x;
    if (i < n) { g_deg_in[i] = 0; g_deg_out[i] = 0; g_cursor[i] = 0; }
}

__global__ void k_degree(const int* __restrict__ src,
                         const int* __restrict__ dst, int e) {
    int i = blockIdx.x * blockDim.x + threadIdx.x;
    if (i < e) {
        int s = src[i];
        int d = dst[i];
        if ((unsigned)s < NN) atomicAdd(&g_deg_out[s], 1);
        if ((unsigned)d < NN) atomicAdd(&g_deg_in[d], 1);
    }
}

__global__ void k_norm(int n) {
    int i = blockIdx.x * blockDim.x + threadIdx.x;
    if (i < n) {
        int dout = g_deg_out[i]; if (dout < 1) dout = 1;
        int din  = g_deg_in[i];  if (din  < 1) din  = 1;
        g_norm_src[i] = rsqrtf((float)dout);
        g_norm_dst[i] = rsqrtf((float)din);
    }
}

// Single-block exclusive scan of g_deg_in -> g_row_ptr  (n <= 100352)
__global__ void k_scan(int n, int e) {
    __shared__ int smv[1024];
    int t = threadIdx.x;
    int chunk = (n + 1023) >> 10;
    int beg = t * chunk;
    int end = beg + chunk; if (end > n) end = n;
    int s = 0;
    for (int i = beg; i < end; ++i) s += g_deg_in[i];
    smv[t] = s;
    __syncthreads();
    for (int off = 1; off < 1024; off <<= 1) {
        int v = 0;
        if (t >= off) v = smv[t - off];
        __syncthreads();
        if (t >= off) smv[t] += v;
        __syncthreads();
    }
    int run = (t == 0) ? 0 : smv[t - 1];
    for (int i = beg; i < end; ++i) { g_row_ptr[i] = run; run += g_deg_in[i]; }
    if (t == 0) g_row_ptr[n] = e;
}

__global__ void k_fill(const int* __restrict__ src,
                       const int* __restrict__ dst, int e) {
    int i = blockIdx.x * blockDim.x + threadIdx.x;
    if (i < e) {
        int s = src[i];
        int d = dst[i];
        if ((unsigned)d < NN && (unsigned)s < NN) {
            int pos = g_row_ptr[d] + atomicAdd(&g_cursor[d], 1);
            g_csr_src[pos] = s;
        }
    }
}

// ---------------- SpMM 1: agg1[d] = (sum_{s->d} emb[s]*norm_src[s]) * norm_dst[d]
// warp per dst row, 128 floats = 32 lanes x float4, register accumulation (no atomics)
__global__ void k_spmm1(const float* __restrict__ emb, int n) {
    int w = (blockIdx.x * blockDim.x + threadIdx.x) >> 5;
    int lane = threadIdx.x & 31;
    if (w >= n) return;
    int beg = g_row_ptr[w];
    int end = g_row_ptr[w + 1];
    const float4* e4 = (const float4*)emb;
    float4 acc = make_float4(0.f, 0.f, 0.f, 0.f);
    int ed = beg;
    for (; ed + 1 < end; ed += 2) {
        int s0 = g_csr_src[ed];
        int s1 = g_csr_src[ed + 1];
        float n0 = g_norm_src[s0];
        float n1 = g_norm_src[s1];
        float4 v0 = e4[(size_t)s0 * 32 + lane];
        float4 v1 = e4[(size_t)s1 * 32 + lane];
        acc.x = fmaf(v0.x, n0, acc.x); acc.y = fmaf(v0.y, n0, acc.y);
        acc.z = fmaf(v0.z, n0, acc.z); acc.w = fmaf(v0.w, n0, acc.w);
        acc.x = fmaf(v1.x, n1, acc.x); acc.y = fmaf(v1.y, n1, acc.y);
        acc.z = fmaf(v1.z, n1, acc.z); acc.w = fmaf(v1.w, n1, acc.w);
    }
    if (ed < end) {
        int s0 = g_csr_src[ed];
        float n0 = g_norm_src[s0];
        float4 v0 = e4[(size_t)s0 * 32 + lane];
        acc.x = fmaf(v0.x, n0, acc.x); acc.y = fmaf(v0.y, n0, acc.y);
        acc.z = fmaf(v0.z, n0, acc.z); acc.w = fmaf(v0.w, n0, acc.w);
    }
    float nd = g_norm_dst[w];
    acc.x *= nd; acc.y *= nd; acc.z *= nd; acc.w *= nd;
    ((float4*)g_agg1)[(size_t)w * 32 + lane] = acc;
}

// ---------------- GEMM1: h1 = relu(agg1 @ W1 + b1)   [N,128]@[128,128]
// 256 threads, block tile 64 rows x 128 cols, static smem 48KB:
//   As[64][128] resident (32KB) + Ws[32][128] k-chunked (16KB)
__global__ void __launch_bounds__(256)
k_gemm1(const float* __restrict__ W, const float* __restrict__ bias, int n) {
    __shared__ float As[64 * 128];
    __shared__ float Ws[32 * 128];
    const int tid = threadIdx.x;
    const int row0 = blockIdx.x * 64;

    // load A tile (64 rows x 128 cols) = 2048 float4
    for (int i = tid; i < 2048; i += 256) {
        int r = i >> 5;
        int gr = row0 + r;
        float4 v = make_float4(0.f, 0.f, 0.f, 0.f);
        if (gr < n) v = ((const float4*)g_agg1)[(size_t)gr * 32 + (i & 31)];
        ((float4*)As)[i] = v;
    }

    const int tc = (tid & 31) << 2;  // 0..124
    const int tr = (tid >> 5) << 3;  // 0..56
    float acc[8][4];
#pragma unroll
    for (int i = 0; i < 8; i++)
#pragma unroll
        for (int j = 0; j < 4; j++) acc[i][j] = 0.f;

    for (int kc = 0; kc < 4; ++kc) {
        __syncthreads();
        // load W chunk rows [kc*32, kc*32+32) : 1024 float4
        for (int i = tid; i < 1024; i += 256)
            ((float4*)Ws)[i] = ((const float4*)W)[kc * 1024 + i];
        __syncthreads();
#pragma unroll
        for (int k = 0; k < 32; ++k) {
            float4 w = *(const float4*)(Ws + k * 128 + tc);
            float a[8];
            int kk = kc * 32 + k;
#pragma unroll
            for (int i = 0; i < 8; i++) a[i] = As[(tr + i) * 128 + kk];
#pragma unroll
            for (int i = 0; i < 8; i++) {
                acc[i][0] = fmaf(a[i], w.x, acc[i][0]);
                acc[i][1] = fmaf(a[i], w.y, acc[i][1]);
                acc[i][2] = fmaf(a[i], w.z, acc[i][2]);
                acc[i][3] = fmaf(a[i], w.w, acc[i][3]);
            }
        }
    }

    float4 bb = *(const float4*)(bias + tc);
#pragma unroll
    for (int i = 0; i < 8; i++) {
        int gr = row0 + tr + i;
        if (gr < n) {
            float4 o;
            o.x = fmaxf(acc[i][0] + bb.x, 0.f);
            o.y = fmaxf(acc[i][1] + bb.y, 0.f);
            o.z = fmaxf(acc[i][2] + bb.z, 0.f);
            o.w = fmaxf(acc[i][3] + bb.w, 0.f);
            *(float4*)(g_h1 + (size_t)gr * 128 + tc) = o;
        }
    }
}

// ---------------- GEMM2: t = (h1 @ W2) * norm_src[:,None]   [N,128]@[128,64]
// 256 threads, block tile 128 rows x 64 cols, static smem 48KB:
//   Ws[128][64] resident (32KB) + As[128][32] k-chunked (16KB)
__global__ void __launch_bounds__(256)
k_gemm2(const float* __restrict__ W2, int n) {
    __shared__ float Ws[128 * 64];
    __shared__ float As[128 * 32];
    const int tid = threadIdx.x;
    const int row0 = blockIdx.x * 128;

    // load full W2 (128x64) = 2048 float4
    for (int i = tid; i < 2048; i += 256)
        ((float4*)Ws)[i] = ((const float4*)W2)[i];

    const int tc = (tid & 15) << 2;  // 0..60
    const int tr = (tid >> 4) << 3;  // 0..120
    float acc[8][4];
#pragma unroll
    for (int i = 0; i < 8; i++)
#pragma unroll
        for (int j = 0; j < 4; j++) acc[i][j] = 0.f;

    for (int kc = 0; kc < 4; ++kc) {
        __syncthreads();
        // load A chunk: 128 rows x 32 cols = 1024 float4 (8 float4 per row)
        for (int i = tid; i < 1024; i += 256) {
            int r = i >> 3;
            int gr = row0 + r;
            float4 v = make_float4(0.f, 0.f, 0.f, 0.f);
            if (gr < n)
                v = *(const float4*)(g_h1 + (size_t)gr * 128 + kc * 32 + ((i & 7) << 2));
            ((float4*)As)[i] = v;
        }
        __syncthreads();
#pragma unroll
        for (int k = 0; k < 32; ++k) {
            float4 w = *(const float4*)(Ws + (kc * 32 + k) * 64 + tc);
            float a[8];
#pragma unroll
            for (int i = 0; i < 8; i++) a[i] = As[(tr + i) * 32 + k];
#pragma unroll
            for (int i = 0; i < 8; i++) {
                acc[i][0] = fmaf(a[i], w.x, acc[i][0]);
                acc[i][1] = fmaf(a[i], w.y, acc[i][1]);
                acc[i][2] = fmaf(a[i], w.z, acc[i][2]);
                acc[i][3] = fmaf(a[i], w.w, acc[i][3]);
            }
        }
    }

#pragma unroll
    for (int i = 0; i < 8; i++) {
        int gr = row0 + tr + i;
        if (gr < n) {
            float ns = g_norm_src[gr];
            float4 o;
            o.x = acc[i][0] * ns;
            o.y = acc[i][1] * ns;
            o.z = acc[i][2] * ns;
            o.w = acc[i][3] * ns;
            *(float4*)(g_t + (size_t)gr * 64 + tc) = o;
        }
    }
}

// ---------------- SpMM 2: out[d] = (sum_{s->d} t[s]) * norm_dst[d] + b2
// warp per dst row, 64 floats = 32 lanes x float2
__global__ void k_spmm2(const float* __restrict__ b2, float* __restrict__ out, int n) {
    int w = (blockIdx.x * blockDim.x + threadIdx.x) >> 5;
    int lane = threadIdx.x & 31;
    if (w >= n) return;
    int beg = g_row_ptr[w];
    int end = g_row_ptr[w + 1];
    const float2* t2 = (const float2*)g_t;
    float2 acc = make_float2(0.f, 0.f);
    int ed = beg;
    for (; ed + 1 < end; ed += 2) {
        int s0 = g_csr_src[ed];
        int s1 = g_csr_src[ed + 1];
        float2 v0 = t2[(size_t)s0 * 32 + lane];
        float2 v1 = t2[(size_t)s1 * 32 + lane];
        acc.x += v0.x + v1.x;
        acc.y += v0.y + v1.y;
    }
    if (ed < end) {
        int s0 = g_csr_src[ed];
        float2 v0 = t2[(size_t)s0 * 32 + lane];
        acc.x += v0.x;
        acc.y += v0.y;
    }
    float nd = g_norm_dst[w];
    float2 bb = ((const float2*)b2)[lane];
    float2 o;
    o.x = fmaf(acc.x, nd, bb.x);
    o.y = fmaf(acc.y, nd, bb.y);
    ((float2*)out)[(size_t)w * 32 + lane] = o;
}

// ---------------- launch ----------------
extern "C" void kernel_launch(void* const* d_in, const int* in_sizes, int n_in,
                              void* d_out, int out_size) {
    // inputs: node_ids(i32), src(i32), dst(i32), emb(f32), W1, b1, W2, b2
    // NOTE: JAX default (x64 disabled) downcasts the reference's int64 arrays
    // to int32; the harness dtype list only contains int32 for integers.
    const int* src = (const int*)d_in[1];
    const int* dst = (const int*)d_in[2];
    const float* emb = (const float*)d_in[3];
    const float* W1  = (const float*)d_in[4];
    const float* b1  = (const float*)d_in[5];
    const float* W2  = (const float*)d_in[6];
    const float* b2  = (const float*)d_in[7];
    float* out = (float*)d_out;

    const int n = in_sizes[0];
    const int e = in_sizes[1];

    k_zero<<<(n + 255) / 256, 256>>>(n);
    k_degree<<<(e + 255) / 256, 256>>>(src, dst, e);
    k_norm<<<(n + 255) / 256, 256>>>(n);
    k_scan<<<1, 1024>>>(n, e);
    k_fill<<<(e + 255) / 256, 256>>>(src, dst, e);

    int warps_grid = (n * 32 + 255) / 256;
    k_spmm1<<<warps_grid, 256>>>(emb, n);
    k_gemm1<<<(n + 63) / 64, 256>>>(W1, b1, n);
    k_gemm2<<<(n + 127) / 128, 256>>>(W2, n);
    k_spmm2<<<warps_grid, 256>>>(b2, out, n);
}

// round 4
// speedup vs baseline: 1.3009x; 1.3009x over previous
#include <cuda_runtime.h>

#define NN 100000
#define NE 1600000
#define SCAN_TILE 1024
#define SCAN_NB ((NN + SCAN_TILE - 1) / SCAN_TILE)   // 98

// ---------------- device scratch (static allocation, allowed) ----------------
__device__ int   g_deg_in[NN];
__device__ int   g_deg_out[NN];
__device__ int   g_cursor[NN];
__device__ float g_norm_src[NN];
__device__ float g_norm_dst[NN];
__device__ int   g_row_ptr[NN + 1];
__device__ int   g_csr_src[NE];
__device__ int   g_blk_sum[SCAN_NB];
__device__ int   g_blk_off[SCAN_NB];
__device__ float g_agg1[(size_t)NN * 128];
__device__ float g_h1[(size_t)NN * 128];
__device__ float g_t[(size_t)NN * 64];

// ---------------- small setup kernels ----------------
__global__ void k_zero(int n) {
    int i = blockIdx.x * blockDim.x + threadIdx.x;
    if (i < n) { g_deg_in[i] = 0; g_deg_out[i] = 0; g_cursor[i] = 0; }
}

__global__ void k_degree(const int* __restrict__ src,
                         const int* __restrict__ dst, int e) {
    int i = blockIdx.x * blockDim.x + threadIdx.x;
    if (i < e) {
        int s = src[i];
        int d = dst[i];
        if ((unsigned)s < NN) atomicAdd(&g_deg_out[s], 1);
        if ((unsigned)d < NN) atomicAdd(&g_deg_in[d], 1);
    }
}

__global__ void k_norm(int n) {
    int i = blockIdx.x * blockDim.x + threadIdx.x;
    if (i < n) {
        int dout = g_deg_out[i]; if (dout < 1) dout = 1;
        int din  = g_deg_in[i];  if (din  < 1) din  = 1;
        g_norm_src[i] = rsqrtf((float)dout);
        g_norm_dst[i] = rsqrtf((float)din);
    }
}

// ---------------- 3-phase exclusive scan of g_deg_in -> g_row_ptr ----------------
// Phase 1: per-block (1024 elems) reduction
__global__ void __launch_bounds__(256)
k_scan_partial(int n) {
    __shared__ int sm[256];
    int t = threadIdx.x;
    int base = blockIdx.x * SCAN_TILE + t * 4;
    int s = 0;
#pragma unroll
    for (int j = 0; j < 4; j++) {
        int i = base + j;
        if (i < n) s += g_deg_in[i];
    }
    sm[t] = s;
    __syncthreads();
    for (int off = 128; off > 0; off >>= 1) {
        if (t < off) sm[t] += sm[t + off];
        __syncthreads();
    }
    if (t == 0) g_blk_sum[blockIdx.x] = sm[0];
}

// Phase 2: single block scans the SCAN_NB block sums (exclusive)
__global__ void __launch_bounds__(128)
k_scan_blk(int n, int e) {
    __shared__ int sm[128];
    int t = threadIdx.x;
    int v = (t < SCAN_NB) ? g_blk_sum[t] : 0;
    sm[t] = v;
    __syncthreads();
    for (int off = 1; off < 128; off <<= 1) {
        int add = 0;
        if (t >= off) add = sm[t - off];
        __syncthreads();
        sm[t] += add;
        __syncthreads();
    }
    if (t < SCAN_NB) g_blk_off[t] = sm[t] - v;  // exclusive
    if (t == 0) g_row_ptr[n] = e;
}

// Phase 3: in-block exclusive scan + block offset -> g_row_ptr
__global__ void __launch_bounds__(256)
k_scan_final(int n) {
    __shared__ int sm[256];
    int t = threadIdx.x;
    int base = blockIdx.x * SCAN_TILE + t * 4;
    int d[4];
    int s = 0;
#pragma unroll
    for (int j = 0; j < 4; j++) {
        int i = base + j;
        d[j] = (i < n) ? g_deg_in[i] : 0;
        s += d[j];
    }
    sm[t] = s;
    __syncthreads();
    for (int off = 1; off < 256; off <<= 1) {
        int add = 0;
        if (t >= off) add = sm[t - off];
        __syncthreads();
        sm[t] += add;
        __syncthreads();
    }
    int run = g_blk_off[blockIdx.x] + sm[t] - s;  // exclusive prefix for this thread
#pragma unroll
    for (int j = 0; j < 4; j++) {
        int i = base + j;
        if (i < n) g_row_ptr[i] = run;
        run += d[j];
    }
}

__global__ void k_fill(const int* __restrict__ src,
                       const int* __restrict__ dst, int e) {
    int i = blockIdx.x * blockDim.x + threadIdx.x;
    if (i < e) {
        int s = src[i];
        int d = dst[i];
        if ((unsigned)d < NN && (unsigned)s < NN) {
            int pos = g_row_ptr[d] + atomicAdd(&g_cursor[d], 1);
            g_csr_src[pos] = s;
        }
    }
}

// ---------------- SpMM 1: agg1[d] = (sum_{s->d} emb[s]*norm_src[s]) * norm_dst[d]
// warp per dst row, 128 floats = 32 lanes x float4, register accumulation (no atomics)
__global__ void k_spmm1(const float* __restrict__ emb, int n) {
    int w = (blockIdx.x * blockDim.x + threadIdx.x) >> 5;
    int lane = threadIdx.x & 31;
    if (w >= n) return;
    int beg = g_row_ptr[w];
    int end = g_row_ptr[w + 1];
    const float4* e4 = (const float4*)emb;
    float4 acc = make_float4(0.f, 0.f, 0.f, 0.f);
    int ed = beg;
    for (; ed + 1 < end; ed += 2) {
        int s0 = g_csr_src[ed];
        int s1 = g_csr_src[ed + 1];
        float n0 = g_norm_src[s0];
        float n1 = g_norm_src[s1];
        float4 v0 = e4[(size_t)s0 * 32 + lane];
        float4 v1 = e4[(size_t)s1 * 32 + lane];
        acc.x = fmaf(v0.x, n0, acc.x); acc.y = fmaf(v0.y, n0, acc.y);
        acc.z = fmaf(v0.z, n0, acc.z); acc.w = fmaf(v0.w, n0, acc.w);
        acc.x = fmaf(v1.x, n1, acc.x); acc.y = fmaf(v1.y, n1, acc.y);
        acc.z = fmaf(v1.z, n1, acc.z); acc.w = fmaf(v1.w, n1, acc.w);
    }
    if (ed < end) {
        int s0 = g_csr_src[ed];
        float n0 = g_norm_src[s0];
        float4 v0 = e4[(size_t)s0 * 32 + lane];
        acc.x = fmaf(v0.x, n0, acc.x); acc.y = fmaf(v0.y, n0, acc.y);
        acc.z = fmaf(v0.z, n0, acc.z); acc.w = fmaf(v0.w, n0, acc.w);
    }
    float nd = g_norm_dst[w];
    acc.x *= nd; acc.y *= nd; acc.z *= nd; acc.w *= nd;
    ((float4*)g_agg1)[(size_t)w * 32 + lane] = acc;
}

// ---------------- GEMM1: h1 = relu(agg1 @ W1 + b1)   [N,128]@[128,128]
// 256 threads, block tile 64 rows x 128 cols, static smem 48KB:
//   As[64][128] resident (32KB) + Ws[32][128] k-chunked (16KB)
__global__ void __launch_bounds__(256)
k_gemm1(const float* __restrict__ W, const float* __restrict__ bias, int n) {
    __shared__ float As[64 * 128];
    __shared__ float Ws[32 * 128];
    const int tid = threadIdx.x;
    const int row0 = blockIdx.x * 64;

    // load A tile (64 rows x 128 cols) = 2048 float4
    for (int i = tid; i < 2048; i += 256) {
        int r = i >> 5;
        int gr = row0 + r;
        float4 v = make_float4(0.f, 0.f, 0.f, 0.f);
        if (gr < n) v = ((const float4*)g_agg1)[(size_t)gr * 32 + (i & 31)];
        ((float4*)As)[i] = v;
    }

    const int tc = (tid & 31) << 2;  // 0..124
    const int tr = (tid >> 5) << 3;  // 0..56
    float acc[8][4];
#pragma unroll
    for (int i = 0; i < 8; i++)
#pragma unroll
        for (int j = 0; j < 4; j++) acc[i][j] = 0.f;

    for (int kc = 0; kc < 4; ++kc) {
        __syncthreads();
        // load W chunk rows [kc*32, kc*32+32) : 1024 float4
        for (int i = tid; i < 1024; i += 256)
            ((float4*)Ws)[i] = ((const float4*)W)[kc * 1024 + i];
        __syncthreads();
#pragma unroll
        for (int k = 0; k < 32; ++k) {
            float4 w = *(const float4*)(Ws + k * 128 + tc);
            float a[8];
            int kk = kc * 32 + k;
#pragma unroll
            for (int i = 0; i < 8; i++) a[i] = As[(tr + i) * 128 + kk];
#pragma unroll
            for (int i = 0; i < 8; i++) {
                acc[i][0] = fmaf(a[i], w.x, acc[i][0]);
                acc[i][1] = fmaf(a[i], w.y, acc[i][1]);
                acc[i][2] = fmaf(a[i], w.z, acc[i][2]);
                acc[i][3] = fmaf(a[i], w.w, acc[i][3]);
            }
        }
    }

    float4 bb = *(const float4*)(bias + tc);
#pragma unroll
    for (int i = 0; i < 8; i++) {
        int gr = row0 + tr + i;
        if (gr < n) {
            float4 o;
            o.x = fmaxf(acc[i][0] + bb.x, 0.f);
            o.y = fmaxf(acc[i][1] + bb.y, 0.f);
            o.z = fmaxf(acc[i][2] + bb.z, 0.f);
            o.w = fmaxf(acc[i][3] + bb.w, 0.f);
            *(float4*)(g_h1 + (size_t)gr * 128 + tc) = o;
        }
    }
}

// ---------------- GEMM2: t = (h1 @ W2) * norm_src[:,None]   [N,128]@[128,64]
// 256 threads, block tile 128 rows x 64 cols, static smem 48KB:
//   Ws[128][64] resident (32KB) + As[128][32] k-chunked (16KB)
__global__ void __launch_bounds__(256)
k_gemm2(const float* __restrict__ W2, int n) {
    __shared__ float Ws[128 * 64];
    __shared__ float As[128 * 32];
    const int tid = threadIdx.x;
    const int row0 = blockIdx.x * 128;

    // load full W2 (128x64) = 2048 float4
    for (int i = tid; i < 2048; i += 256)
        ((float4*)Ws)[i] = ((const float4*)W2)[i];

    const int tc = (tid & 15) << 2;  // 0..60
    const int tr = (tid >> 4) << 3;  // 0..120
    float acc[8][4];
#pragma unroll
    for (int i = 0; i < 8; i++)
#pragma unroll
        for (int j = 0; j < 4; j++) acc[i][j] = 0.f;

    for (int kc = 0; kc < 4; ++kc) {
        __syncthreads();
        // load A chunk: 128 rows x 32 cols = 1024 float4 (8 float4 per row)
        for (int i = tid; i < 1024; i += 256) {
            int r = i >> 3;
            int gr = row0 + r;
            float4 v = make_float4(0.f, 0.f, 0.f, 0.f);
            if (gr < n)
                v = *(const float4*)(g_h1 + (size_t)gr * 128 + kc * 32 + ((i & 7) << 2));
            ((float4*)As)[i] = v;
        }
        __syncthreads();
#pragma unroll
        for (int k = 0; k < 32; ++k) {
            float4 w = *(const float4*)(Ws + (kc * 32 + k) * 64 + tc);
            float a[8];
#pragma unroll
            for (int i = 0; i < 8; i++) a[i] = As[(tr + i) * 32 + k];
#pragma unroll
            for (int i = 0; i < 8; i++) {
                acc[i][0] = fmaf(a[i], w.x, acc[i][0]);
                acc[i][1] = fmaf(a[i], w.y, acc[i][1]);
                acc[i][2] = fmaf(a[i], w.z, acc[i][2]);
                acc[i][3] = fmaf(a[i], w.w, acc[i][3]);
            }
        }
    }

#pragma unroll
    for (int i = 0; i < 8; i++) {
        int gr = row0 + tr + i;
        if (gr < n) {
            float ns = g_norm_src[gr];
            float4 o;
            o.x = acc[i][0] * ns;
            o.y = acc[i][1] * ns;
            o.z = acc[i][2] * ns;
            o.w = acc[i][3] * ns;
            *(float4*)(g_t + (size_t)gr * 64 + tc) = o;
        }
    }
}

// ---------------- SpMM 2: out[d] = (sum_{s->d} t[s]) * norm_dst[d] + b2
// warp per dst row, 64 floats = 32 lanes x float2
__global__ void k_spmm2(const float* __restrict__ b2, float* __restrict__ out, int n) {
    int w = (blockIdx.x * blockDim.x + threadIdx.x) >> 5;
    int lane = threadIdx.x & 31;
    if (w >= n) return;
    int beg = g_row_ptr[w];
    int end = g_row_ptr[w + 1];
    const float2* t2 = (const float2*)g_t;
    float2 acc = make_float2(0.f, 0.f);
    int ed = beg;
    for (; ed + 1 < end; ed += 2) {
        int s0 = g_csr_src[ed];
        int s1 = g_csr_src[ed + 1];
        float2 v0 = t2[(size_t)s0 * 32 + lane];
        float2 v1 = t2[(size_t)s1 * 32 + lane];
        acc.x += v0.x + v1.x;
        acc.y += v0.y + v1.y;
    }
    if (ed < end) {
        int s0 = g_csr_src[ed];
        float2 v0 = t2[(size_t)s0 * 32 + lane];
        acc.x += v0.x;
        acc.y += v0.y;
    }
    float nd = g_norm_dst[w];
    float2 bb = ((const float2*)b2)[lane];
    float2 o;
    o.x = fmaf(acc.x, nd, bb.x);
    o.y = fmaf(acc.y, nd, bb.y);
    ((float2*)out)[(size_t)w * 32 + lane] = o;
}

// ---------------- launch ----------------
extern "C" void kernel_launch(void* const* d_in, const int* in_sizes, int n_in,
                              void* d_out, int out_size) {
    // inputs: node_ids(i32), src(i32), dst(i32), emb(f32), W1, b1, W2, b2
    const int* src = (const int*)d_in[1];
    const int* dst = (const int*)d_in[2];
    const float* emb = (const float*)d_in[3];
    const float* W1  = (const float*)d_in[4];
    const float* b1  = (const float*)d_in[5];
    const float* W2  = (const float*)d_in[6];
    const float* b2  = (const float*)d_in[7];
    float* out = (float*)d_out;

    const int n = in_sizes[0];
    const int e = in_sizes[1];

    k_zero<<<(n + 255) / 256, 256>>>(n);
    k_degree<<<(e + 255) / 256, 256>>>(src, dst, e);
    k_norm<<<(n + 255) / 256, 256>>>(n);
    k_scan_partial<<<SCAN_NB, 256>>>(n);
    k_scan_blk<<<1, 128>>>(n, e);
    k_scan_final<<<SCAN_NB, 256>>>(n);
    k_fill<<<(e + 255) / 256, 256>>>(src, dst, e);

    int warps_grid = (n * 32 + 255) / 256;
    k_spmm1<<<warps_grid, 256>>>(emb, n);
    k_gemm1<<<(n + 63) / 64, 256>>>(W1, b1, n);
    k_gemm2<<<(n + 127) / 128, 256>>>(W2, n);
    k_spmm2<<<warps_grid, 256>>>(b2, out, n);
}

// round 5
// speedup vs baseline: 1.4415x; 1.1080x over previous
#include <cuda_runtime.h>
#include <cuda_fp16.h>

#define NN 100000
#define NE 1600000
#define SCAN_TILE 1024
#define SCAN_NB ((NN + SCAN_TILE - 1) / SCAN_TILE)   // 98

// packed fp32x2 FMA (sm_103a FFMA2) — full fp32 precision, 2 FMAs/instr
#define FMA_F32X2(d, a, b, c) \
    asm("fma.rn.f32x2 %0, %1, %2, %3;" : "=l"(d) : "l"(a), "l"(b), "l"(c))
#define PACK2(out, lo, hi) \
    asm("mov.b64 %0, {%1, %2};" : "=l"(out) : "r"(__float_as_uint(lo)), "r"(__float_as_uint(hi)))
#define UNPACK2(lo, hi, in) \
    do { unsigned _l, _h; asm("mov.b64 {%0, %1}, %2;" : "=r"(_l), "=r"(_h) : "l"(in)); \
         lo = __uint_as_float(_l); hi = __uint_as_float(_h); } while (0)

// ---------------- device scratch ----------------
__device__ int     g_deg_in[NN];
__device__ int     g_deg_out[NN];
__device__ int     g_cursor[NN];
__device__ float   g_norm_src[NN];
__device__ float   g_norm_dst[NN];
__device__ int     g_row_ptr[NN + 1];
__device__ int     g_csr_src[NE];
__device__ int     g_blk_sum[SCAN_NB];
__device__ int     g_blk_off[SCAN_NB];
__device__ __half2 g_emb_h[(size_t)NN * 64];   // emb * norm_src, fp16
__device__ float   g_agg1[(size_t)NN * 128];
__device__ __half2 g_t_h[(size_t)NN * 32];     // (h1@W2)*norm_src, fp16

// ---------------- setup ----------------
__global__ void k_zero(int n) {
    int i = blockIdx.x * blockDim.x + threadIdx.x;
    if (i < n) { g_deg_in[i] = 0; g_deg_out[i] = 0; g_cursor[i] = 0; }
}

__global__ void k_degree(const int* __restrict__ src,
                         const int* __restrict__ dst, int e) {
    int i = blockIdx.x * blockDim.x + threadIdx.x;
    if (i < e) {
        int s = src[i];
        int d = dst[i];
        if ((unsigned)s < NN) atomicAdd(&g_deg_out[s], 1);
        if ((unsigned)d < NN) atomicAdd(&g_deg_in[d], 1);
    }
}

__global__ void k_norm(int n) {
    int i = blockIdx.x * blockDim.x + threadIdx.x;
    if (i < n) {
        int dout = g_deg_out[i]; if (dout < 1) dout = 1;
        int din  = g_deg_in[i];  if (din  < 1) din  = 1;
        g_norm_src[i] = rsqrtf((float)dout);
        g_norm_dst[i] = rsqrtf((float)din);
    }
}

// emb * norm_src -> half2 (one half2 per thread)
__global__ void k_prep(const float* __restrict__ emb, int n64) {
    int i = blockIdx.x * blockDim.x + threadIdx.x;
    if (i < n64) {
        int r = i >> 6;
        float2 v = ((const float2*)emb)[i];
        float ns = g_norm_src[r];
        g_emb_h[i] = __floats2half2_rn(v.x * ns, v.y * ns);
    }
}

// ---------------- 3-phase exclusive scan ----------------
__global__ void __launch_bounds__(256)
k_scan_partial(int n) {
    __shared__ int sm[256];
    int t = threadIdx.x;
    int base = blockIdx.x * SCAN_TILE + t * 4;
    int s = 0;
#pragma unroll
    for (int j = 0; j < 4; j++) {
        int i = base + j;
        if (i < n) s += g_deg_in[i];
    }
    sm[t] = s;
    __syncthreads();
    for (int off = 128; off > 0; off >>= 1) {
        if (t < off) sm[t] += sm[t + off];
        __syncthreads();
    }
    if (t == 0) g_blk_sum[blockIdx.x] = sm[0];
}

__global__ void __launch_bounds__(128)
k_scan_blk(int n, int e) {
    __shared__ int sm[128];
    int t = threadIdx.x;
    int v = (t < SCAN_NB) ? g_blk_sum[t] : 0;
    sm[t] = v;
    __syncthreads();
    for (int off = 1; off < 128; off <<= 1) {
        int add = 0;
        if (t >= off) add = sm[t - off];
        __syncthreads();
        sm[t] += add;
        __syncthreads();
    }
    if (t < SCAN_NB) g_blk_off[t] = sm[t] - v;
    if (t == 0) g_row_ptr[n] = e;
}

__global__ void __launch_bounds__(256)
k_scan_final(int n) {
    __shared__ int sm[256];
    int t = threadIdx.x;
    int base = blockIdx.x * SCAN_TILE + t * 4;
    int d[4];
    int s = 0;
#pragma unroll
    for (int j = 0; j < 4; j++) {
        int i = base + j;
        d[j] = (i < n) ? g_deg_in[i] : 0;
        s += d[j];
    }
    sm[t] = s;
    __syncthreads();
    for (int off = 1; off < 256; off <<= 1) {
        int add = 0;
        if (t >= off) add = sm[t - off];
        __syncthreads();
        sm[t] += add;
        __syncthreads();
    }
    int run = g_blk_off[blockIdx.x] + sm[t] - s;
#pragma unroll
    for (int j = 0; j < 4; j++) {
        int i = base + j;
        if (i < n) g_row_ptr[i] = run;
        run += d[j];
    }
}

__global__ void k_fill(const int* __restrict__ src,
                       const int* __restrict__ dst, int e) {
    int i = blockIdx.x * blockDim.x + threadIdx.x;
    if (i < e) {
        int s = src[i];
        int d = dst[i];
        if ((unsigned)d < NN && (unsigned)s < NN) {
            int pos = g_row_ptr[d] + atomicAdd(&g_cursor[d], 1);
            g_csr_src[pos] = s;
        }
    }
}

// ---------------- SpMM 1: agg1[d] = (sum emb_h[s]) * norm_dst[d]  (fp16 gather)
// warp per dst row; lane loads uint2 = 4 features, fp32 accumulate
__global__ void k_spmm1(int n) {
    int w = (blockIdx.x * blockDim.x + threadIdx.x) >> 5;
    int lane = threadIdx.x & 31;
    if (w >= n) return;
    int beg = g_row_ptr[w];
    int end = g_row_ptr[w + 1];
    const uint2* eh = (const uint2*)g_emb_h;   // row = 32 uint2
    float4 acc = make_float4(0.f, 0.f, 0.f, 0.f);
    int ed = beg;
    for (; ed + 1 < end; ed += 2) {
        int s0 = g_csr_src[ed];
        int s1 = g_csr_src[ed + 1];
        uint2 v0 = eh[(size_t)s0 * 32 + lane];
        uint2 v1 = eh[(size_t)s1 * 32 + lane];
        float2 a0 = __half22float2(*(__half2*)&v0.x);
        float2 b0 = __half22float2(*(__half2*)&v0.y);
        float2 a1 = __half22float2(*(__half2*)&v1.x);
        float2 b1 = __half22float2(*(__half2*)&v1.y);
        acc.x += a0.x + a1.x; acc.y += a0.y + a1.y;
        acc.z += b0.x + b1.x; acc.w += b0.y + b1.y;
    }
    if (ed < end) {
        int s0 = g_csr_src[ed];
        uint2 v0 = eh[(size_t)s0 * 32 + lane];
        float2 a0 = __half22float2(*(__half2*)&v0.x);
        float2 b0 = __half22float2(*(__half2*)&v0.y);
        acc.x += a0.x; acc.y += a0.y; acc.z += b0.x; acc.w += b0.y;
    }
    float nd = g_norm_dst[w];
    acc.x *= nd; acc.y *= nd; acc.z *= nd; acc.w *= nd;
    ((float4*)g_agg1)[(size_t)w * 32 + lane] = acc;
}

// ---------------- fused GEMM: t_h = relu(agg1@W1+b1) @ W2 * norm_src  (FFMA2)
// 256 threads, 64-row tile. As/Hs stored k-major, padded stride 68.
#define APAD 68
__global__ void __launch_bounds__(256)
k_gemm_fused(const float* __restrict__ W1, const float* __restrict__ b1,
             const float* __restrict__ W2, int n) {
    __shared__ float As[128 * APAD];   // k-major A tile, reused as Hs
    __shared__ float Ws[2048];         // 16x128 W1 chunk / 32x64 W2 chunk
    const int tid = threadIdx.x;
    const int row0 = blockIdx.x * 64;

    // load A tile transposed: As[k][r]
    for (int i = tid; i < 2048; i += 256) {
        int r = i >> 5;
        int gr = row0 + r;
        int kq = i & 31;
        float4 v = make_float4(0.f, 0.f, 0.f, 0.f);
        if (gr < n) v = ((const float4*)g_agg1)[(size_t)gr * 32 + kq];
        As[(kq * 4 + 0) * APAD + r] = v.x;
        As[(kq * 4 + 1) * APAD + r] = v.y;
        As[(kq * 4 + 2) * APAD + r] = v.z;
        As[(kq * 4 + 3) * APAD + r] = v.w;
    }

    // ---- phase 1: h1 = relu(A @ W1 + b1), 64x128 tile ----
    const int tc = (tid & 31) << 2;  // col 0..124
    const int tr = (tid >> 5) << 3;  // row 0..56
    unsigned long long acc1[4][4];   // [col j][row pair p]
#pragma unroll
    for (int j = 0; j < 4; j++)
#pragma unroll
        for (int p = 0; p < 4; p++) acc1[j][p] = 0ull;

    for (int kc = 0; kc < 8; ++kc) {
        __syncthreads();
        for (int i = tid; i < 512; i += 256)
            ((float4*)Ws)[i] = ((const float4*)W1)[kc * 512 + i];
        __syncthreads();
#pragma unroll
        for (int k = 0; k < 16; ++k) {
            int kk = kc * 16 + k;
            ulonglong2 aA = *(const ulonglong2*)(As + kk * APAD + tr);      // rows tr..tr+3
            ulonglong2 aB = *(const ulonglong2*)(As + kk * APAD + tr + 4);  // rows tr+4..tr+7
            float4 wv = *(const float4*)(Ws + k * 128 + tc);
            unsigned long long wd[4];
            PACK2(wd[0], wv.x, wv.x);
            PACK2(wd[1], wv.y, wv.y);
            PACK2(wd[2], wv.z, wv.z);
            PACK2(wd[3], wv.w, wv.w);
#pragma unroll
            for (int j = 0; j < 4; j++) {
                FMA_F32X2(acc1[j][0], aA.x, wd[j], acc1[j][0]);
                FMA_F32X2(acc1[j][1], aA.y, wd[j], acc1[j][1]);
                FMA_F32X2(acc1[j][2], aB.x, wd[j], acc1[j][2]);
                FMA_F32X2(acc1[j][3], aB.y, wd[j], acc1[j][3]);
            }
        }
    }

    __syncthreads();  // all As reads done before overwrite
    {
        float4 bb = *(const float4*)(b1 + tc);
        float bj[4] = {bb.x, bb.y, bb.z, bb.w};
#pragma unroll
        for (int j = 0; j < 4; j++) {
#pragma unroll
            for (int p = 0; p < 4; p++) {
                float lo, hi;
                UNPACK2(lo, hi, acc1[j][p]);
                As[(tc + j) * APAD + tr + 2 * p]     = fmaxf(lo + bj[j], 0.f);
                As[(tc + j) * APAD + tr + 2 * p + 1] = fmaxf(hi + bj[j], 0.f);
            }
        }
    }

    // ---- phase 2: t = (h1 @ W2) * norm_src, 64x64 tile ----
    const int tc2 = (tid & 15) << 2;  // col 0..60
    const int tr2 = (tid >> 4) << 2;  // row 0..60
    unsigned long long acc2[4][2];
#pragma unroll
    for (int j = 0; j < 4; j++) { acc2[j][0] = 0ull; acc2[j][1] = 0ull; }

    for (int kc = 0; kc < 4; ++kc) {
        __syncthreads();
        for (int i = tid; i < 512; i += 256)
            ((float4*)Ws)[i] = ((const float4*)W2)[kc * 512 + i];
        __syncthreads();
#pragma unroll
        for (int k = 0; k < 32; ++k) {
            int kk = kc * 32 + k;
            ulonglong2 a = *(const ulonglong2*)(As + kk * APAD + tr2);  // rows tr2..tr2+3
            float4 wv = *(const float4*)(Ws + k * 64 + tc2);
            unsigned long long wd[4];
            PACK2(wd[0], wv.x, wv.x);
            PACK2(wd[1], wv.y, wv.y);
            PACK2(wd[2], wv.z, wv.z);
            PACK2(wd[3], wv.w, wv.w);
#pragma unroll
            for (int j = 0; j < 4; j++) {
                FMA_F32X2(acc2[j][0], a.x, wd[j], acc2[j][0]);
                FMA_F32X2(acc2[j][1], a.y, wd[j], acc2[j][1]);
            }
        }
    }

#pragma unroll
    for (int p = 0; p < 2; p++) {
        int gr0 = row0 + tr2 + 2 * p;
        int gr1 = gr0 + 1;
        float ns0 = (gr0 < n) ? g_norm_src[gr0] : 0.f;
        float ns1 = (gr1 < n) ? g_norm_src[gr1] : 0.f;
        float r0v[4], r1v[4];
#pragma unroll
        for (int j = 0; j < 4; j++) {
            float lo, hi;
            UNPACK2(lo, hi, acc2[j][p]);
            r0v[j] = lo * ns0;
            r1v[j] = hi * ns1;
        }
        if (gr0 < n) {
            g_t_h[(size_t)gr0 * 32 + (tc2 >> 1)]     = __floats2half2_rn(r0v[0], r0v[1]);
            g_t_h[(size_t)gr0 * 32 + (tc2 >> 1) + 1] = __floats2half2_rn(r0v[2], r0v[3]);
        }
        if (gr1 < n) {
            g_t_h[(size_t)gr1 * 32 + (tc2 >> 1)]     = __floats2half2_rn(r1v[0], r1v[1]);
            g_t_h[(size_t)gr1 * 32 + (tc2 >> 1) + 1] = __floats2half2_rn(r1v[2], r1v[3]);
        }
    }
}

// ---------------- SpMM 2: out[d] = (sum t_h[s]) * norm_dst[d] + b2  (fp16 gather)
// warp per dst row; lane loads one half2 (2 features)
__global__ void k_spmm2(const float* __restrict__ b2, float* __restrict__ out, int n) {
    int w = (blockIdx.x * blockDim.x + threadIdx.x) >> 5;
    int lane = threadIdx.x & 31;
    if (w >= n) return;
    int beg = g_row_ptr[w];
    int end = g_row_ptr[w + 1];
    float2 acc = make_float2(0.f, 0.f);
    int ed = beg;
    for (; ed + 1 < end; ed += 2) {
        int s0 = g_csr_src[ed];
        int s1 = g_csr_src[ed + 1];
        float2 v0 = __half22float2(g_t_h[(size_t)s0 * 32 + lane]);
        float2 v1 = __half22float2(g_t_h[(size_t)s1 * 32 + lane]);
        acc.x += v0.x + v1.x;
        acc.y += v0.y + v1.y;
    }
    if (ed < end) {
        int s0 = g_csr_src[ed];
        float2 v0 = __half22float2(g_t_h[(size_t)s0 * 32 + lane]);
        acc.x += v0.x;
        acc.y += v0.y;
    }
    float nd = g_norm_dst[w];
    float2 bb = ((const float2*)b2)[lane];
    float2 o;
    o.x = fmaf(acc.x, nd, bb.x);
    o.y = fmaf(acc.y, nd, bb.y);
    ((float2*)out)[(size_t)w * 32 + lane] = o;
}

// ---------------- launch ----------------
extern "C" void kernel_launch(void* const* d_in, const int* in_sizes, int n_in,
                              void* d_out, int out_size) {
    const int* src = (const int*)d_in[1];
    const int* dst = (const int*)d_in[2];
    const float* emb = (const float*)d_in[3];
    const float* W1  = (const float*)d_in[4];
    const float* b1  = (const float*)d_in[5];
    const float* W2  = (const float*)d_in[6];
    const float* b2  = (const float*)d_in[7];
    float* out = (float*)d_out;

    const int n = in_sizes[0];
    const int e = in_sizes[1];

    k_zero<<<(n + 255) / 256, 256>>>(n);
    k_degree<<<(e + 255) / 256, 256>>>(src, dst, e);
    k_norm<<<(n + 255) / 256, 256>>>(n);
    k_prep<<<(n * 64 + 255) / 256, 256>>>(emb, n * 64);
    k_scan_partial<<<SCAN_NB, 256>>>(n);
    k_scan_blk<<<1, 128>>>(n, e);
    k_scan_final<<<SCAN_NB, 256>>>(n);
    k_fill<<<(e + 255) / 256, 256>>>(src, dst, e);

    int warps_grid = (n * 32 + 255) / 256;
    k_spmm1<<<warps_grid, 256>>>(n);
    k_gemm_fused<<<(n + 63) / 64, 256>>>(W1, b1, W2, n);
    k_spmm2<<<warps_grid, 256>>>(b2, out, n);
}

// round 7
// speedup vs baseline: 2.0296x; 1.4080x over previous
#include <cuda_runtime.h>
#include <cuda_fp16.h>
#include <cstdint>

#define NN 100000
#define NE 1600000
#define SCAN_TILE 1024
#define SCAN_NB ((NN + SCAN_TILE - 1) / SCAN_TILE)   // 98

#define APAD 136   // As row stride (halves)
#define WPAD 40    // Wts row stride (halves)

// m16n8k16 fp16 MMA, fp32 accumulate (sm_80+ PTX, works on compute_103)
#define MMA16816(c0, c1, c2, c3, a0, a1, a2, a3, b0, b1) \
    asm volatile("mma.sync.aligned.m16n8k16.row.col.f32.f16.f16.f32 " \
        "{%0,%1,%2,%3}, {%4,%5,%6,%7}, {%8,%9}, {%0,%1,%2,%3};" \
        : "+f"(c0), "+f"(c1), "+f"(c2), "+f"(c3) \
        : "r"(a0), "r"(a1), "r"(a2), "r"(a3), "r"(b0), "r"(b1))

// ---------------- device scratch ----------------
__device__ int     g_deg_in[NN];
__device__ int     g_deg_out[NN];
__device__ int     g_cursor[NN];
__device__ float   g_norm_src[NN];
__device__ float   g_norm_dst[NN];
__device__ int     g_row_ptr[NN + 1];
__device__ int     g_csr_src[NE];
__device__ int     g_blk_sum[SCAN_NB];
__device__ int     g_blk_off[SCAN_NB];
__device__ __half2 g_emb_h[(size_t)NN * 64];   // emb * norm_src, fp16
__device__ __half2 g_agg_h[(size_t)NN * 64];   // spmm1 result, fp16
__device__ __half2 g_t_h[(size_t)NN * 32];     // (h1@W2)*norm_src, fp16

// ---------------- setup ----------------
__global__ void k_zero(int n) {
    int i = blockIdx.x * blockDim.x + threadIdx.x;
    if (i < n) { g_deg_in[i] = 0; g_deg_out[i] = 0; g_cursor[i] = 0; }
}

__global__ void k_degree(const int* __restrict__ src,
                         const int* __restrict__ dst, int e) {
    int i = blockIdx.x * blockDim.x + threadIdx.x;
    if (i < e) {
        int s = src[i];
        int d = dst[i];
        if ((unsigned)s < NN) atomicAdd(&g_deg_out[s], 1);
        if ((unsigned)d < NN) atomicAdd(&g_deg_in[d], 1);
    }
}

__global__ void k_norm(int n) {
    int i = blockIdx.x * blockDim.x + threadIdx.x;
    if (i < n) {
        int dout = g_deg_out[i]; if (dout < 1) dout = 1;
        int din  = g_deg_in[i];  if (din  < 1) din  = 1;
        g_norm_src[i] = rsqrtf((float)dout);
        g_norm_dst[i] = rsqrtf((float)din);
    }
}

// emb * norm_src -> half2, float4-wide
__global__ void k_prep(const float* __restrict__ emb, int n32) {
    int i = blockIdx.x * blockDim.x + threadIdx.x;   // one per 4 feats
    if (i < n32) {
        int r = i >> 5;
        float4 v = ((const float4*)emb)[i];
        float ns = g_norm_src[r];
        uint2 o;
        *(__half2*)&o.x = __floats2half2_rn(v.x * ns, v.y * ns);
        *(__half2*)&o.y = __floats2half2_rn(v.z * ns, v.w * ns);
        ((uint2*)g_emb_h)[i] = o;
    }
}

// ---------------- 3-phase exclusive scan ----------------
__global__ void __launch_bounds__(256)
k_scan_partial(int n) {
    __shared__ int sm[256];
    int t = threadIdx.x;
    int base = blockIdx.x * SCAN_TILE + t * 4;
    int s = 0;
#pragma unroll
    for (int j = 0; j < 4; j++) {
        int i = base + j;
        if (i < n) s += g_deg_in[i];
    }
    sm[t] = s;
    __syncthreads();
    for (int off = 128; off > 0; off >>= 1) {
        if (t < off) sm[t] += sm[t + off];
        __syncthreads();
    }
    if (t == 0) g_blk_sum[blockIdx.x] = sm[0];
}

__global__ void __launch_bounds__(128)
k_scan_blk(int n, int e) {
    __shared__ int sm[128];
    int t = threadIdx.x;
    int v = (t < SCAN_NB) ? g_blk_sum[t] : 0;
    sm[t] = v;
    __syncthreads();
    for (int off = 1; off < 128; off <<= 1) {
        int add = 0;
        if (t >= off) add = sm[t - off];
        __syncthreads();
        sm[t] += add;
        __syncthreads();
    }
    if (t < SCAN_NB) g_blk_off[t] = sm[t] - v;
    if (t == 0) g_row_ptr[n] = e;
}

__global__ void __launch_bounds__(256)
k_scan_final(int n) {
    __shared__ int sm[256];
    int t = threadIdx.x;
    int base = blockIdx.x * SCAN_TILE + t * 4;
    int d[4];
    int s = 0;
#pragma unroll
    for (int j = 0; j < 4; j++) {
        int i = base + j;
        d[j] = (i < n) ? g_deg_in[i] : 0;
        s += d[j];
    }
    sm[t] = s;
    __syncthreads();
    for (int off = 1; off < 256; off <<= 1) {
        int add = 0;
        if (t >= off) add = sm[t - off];
        __syncthreads();
        sm[t] += add;
        __syncthreads();
    }
    int run = g_blk_off[blockIdx.x] + sm[t] - s;
#pragma unroll
    for (int j = 0; j < 4; j++) {
        int i = base + j;
        if (i < n) g_row_ptr[i] = run;
        run += d[j];
    }
}

__global__ void k_fill(const int* __restrict__ src,
                       const int* __restrict__ dst, int e) {
    int i = blockIdx.x * blockDim.x + threadIdx.x;
    if (i < e) {
        int s = src[i];
        int d = dst[i];
        if ((unsigned)d < NN && (unsigned)s < NN) {
            int pos = g_row_ptr[d] + atomicAdd(&g_cursor[d], 1);
            g_csr_src[pos] = s;
        }
    }
}

// ---------------- SpMM 1 (fp16 gather, fp32 accumulate, fp16 out) ----------------
__global__ void k_spmm1(int n) {
    int w = (blockIdx.x * blockDim.x + threadIdx.x) >> 5;
    int lane = threadIdx.x & 31;
    if (w >= n) return;
    int beg = g_row_ptr[w];
    int end = g_row_ptr[w + 1];
    const uint2* eh = (const uint2*)g_emb_h;   // row = 32 uint2
    float4 acc = make_float4(0.f, 0.f, 0.f, 0.f);
    int ed = beg;
    for (; ed + 1 < end; ed += 2) {
        int s0 = g_csr_src[ed];
        int s1 = g_csr_src[ed + 1];
        uint2 v0 = eh[(size_t)s0 * 32 + lane];
        uint2 v1 = eh[(size_t)s1 * 32 + lane];
        float2 a0 = __half22float2(*(__half2*)&v0.x);
        float2 b0 = __half22float2(*(__half2*)&v0.y);
        float2 a1 = __half22float2(*(__half2*)&v1.x);
        float2 b1 = __half22float2(*(__half2*)&v1.y);
        acc.x += a0.x + a1.x; acc.y += a0.y + a1.y;
        acc.z += b0.x + b1.x; acc.w += b0.y + b1.y;
    }
    if (ed < end) {
        int s0 = g_csr_src[ed];
        uint2 v0 = eh[(size_t)s0 * 32 + lane];
        float2 a0 = __half22float2(*(__half2*)&v0.x);
        float2 b0 = __half22float2(*(__half2*)&v0.y);
        acc.x += a0.x; acc.y += a0.y; acc.z += b0.x; acc.w += b0.y;
    }
    float nd = g_norm_dst[w];
    uint2 o;
    *(__half2*)&o.x = __floats2half2_rn(acc.x * nd, acc.y * nd);
    *(__half2*)&o.y = __floats2half2_rn(acc.z * nd, acc.w * nd);
    ((uint2*)g_agg_h)[(size_t)w * 32 + lane] = o;
}

// ---------------- fused GEMM via HMMA (mma.sync m16n8k16) ----------------
// block = 256 thr (8 warps), 128 rows; warp w owns rows 16w..16w+15.
// phase1: h1 = relu(A @ W1 + b1) -> fp16 back into As (warp-local rows)
// phase2: t  = (h1 @ W2) * norm_src -> g_t_h
__global__ void __launch_bounds__(256)
k_gemm_mma(const float* __restrict__ W1, const float* __restrict__ b1,
           const float* __restrict__ W2, int n) {
    __shared__ __half As[128 * APAD];    // 34.8KB
    __shared__ __half Wts[128 * WPAD];   // 10.2KB, [n][k] transposed chunks
    __shared__ float b1s[128];

    const int tid = threadIdx.x;
    const int lane = tid & 31;
    const int wid = tid >> 5;
    const int row0 = blockIdx.x * 128;
    const int m0 = wid * 16;
    const int r = lane >> 2;          // 0..7
    const int qc = (lane & 3) * 2;    // 0,2,4,6

    // load A tile (fp16, from g_agg_h), zero-pad OOB rows
    for (int i = tid; i < 128 * 32; i += 256) {
        int row = i >> 5, q = i & 31;
        int gr = row0 + row;
        uint2 v = make_uint2(0u, 0u);
        if (gr < n) v = ((const uint2*)g_agg_h)[(size_t)gr * 32 + q];
        *(uint2*)&As[row * APAD + q * 4] = v;
    }
    if (tid < 128) b1s[tid] = b1[tid];

    // ---- phase 1: 16x128 per warp, K=128 ----
    float acc[16][4];
#pragma unroll
    for (int t2 = 0; t2 < 16; t2++)
#pragma unroll
        for (int j = 0; j < 4; j++) acc[t2][j] = 0.f;

    for (int kc = 0; kc < 4; kc++) {
        __syncthreads();
        // Wts[n][kl] = W1[kc*32+kl][n], n<128, kl<32
        for (int i = tid; i < 32 * 128; i += 256) {
            int kl = i >> 7, nn = i & 127;
            Wts[nn * WPAD + kl] = __float2half(W1[(kc * 32 + kl) * 128 + nn]);
        }
        __syncthreads();
#pragma unroll
        for (int ks = 0; ks < 2; ks++) {
            int kb = kc * 32 + ks * 16;
            uint32_t a0 = *(uint32_t*)&As[(m0 + r) * APAD + kb + qc];
            uint32_t a1 = *(uint32_t*)&As[(m0 + r + 8) * APAD + kb + qc];
            uint32_t a2 = *(uint32_t*)&As[(m0 + r) * APAD + kb + qc + 8];
            uint32_t a3 = *(uint32_t*)&As[(m0 + r + 8) * APAD + kb + qc + 8];
            int kw = ks * 16;
#pragma unroll
            for (int nt = 0; nt < 16; nt++) {
                uint32_t b0 = *(uint32_t*)&Wts[(nt * 8 + r) * WPAD + kw + qc];
                uint32_t b1f = *(uint32_t*)&Wts[(nt * 8 + r) * WPAD + kw + qc + 8];
                MMA16816(acc[nt][0], acc[nt][1], acc[nt][2], acc[nt][3],
                         a0, a1, a2, a3, b0, b1f);
            }
        }
    }

    // epilogue 1: relu + bias, write h1 fp16 into As (own rows only)
#pragma unroll
    for (int nt = 0; nt < 16; nt++) {
        int c = nt * 8 + qc;
        float x0 = fmaxf(acc[nt][0] + b1s[c],     0.f);
        float x1 = fmaxf(acc[nt][1] + b1s[c + 1], 0.f);
        float x2 = fmaxf(acc[nt][2] + b1s[c],     0.f);
        float x3 = fmaxf(acc[nt][3] + b1s[c + 1], 0.f);
        *(__half2*)&As[(m0 + r) * APAD + c]     = __floats2half2_rn(x0, x1);
        *(__half2*)&As[(m0 + r + 8) * APAD + c] = __floats2half2_rn(x2, x3);
    }

    // ---- phase 2: 16x64 per warp, K=128 ----
    float acc2[8][4];
#pragma unroll
    for (int t2 = 0; t2 < 8; t2++)
#pragma unroll
        for (int j = 0; j < 4; j++) acc2[t2][j] = 0.f;

    for (int kc = 0; kc < 4; kc++) {
        __syncthreads();   // all warps done with Wts (and h1 writes are warp-local)
        // Wts[n][kl] = W2[kc*32+kl][n], n<64
        for (int i = tid; i < 32 * 64; i += 256) {
            int kl = i >> 6, nn = i & 63;
            Wts[nn * WPAD + kl] = __float2half(W2[(kc * 32 + kl) * 64 + nn]);
        }
        __syncthreads();
#pragma unroll
        for (int ks = 0; ks < 2; ks++) {
            int kb = kc * 32 + ks * 16;
            uint32_t a0 = *(uint32_t*)&As[(m0 + r) * APAD + kb + qc];
            uint32_t a1 = *(uint32_t*)&As[(m0 + r + 8) * APAD + kb + qc];
            uint32_t a2 = *(uint32_t*)&As[(m0 + r) * APAD + kb + qc + 8];
            uint32_t a3 = *(uint32_t*)&As[(m0 + r + 8) * APAD + kb + qc + 8];
            int kw = ks * 16;
#pragma unroll
            for (int nt = 0; nt < 8; nt++) {
                uint32_t b0 = *(uint32_t*)&Wts[(nt * 8 + r) * WPAD + kw + qc];
                uint32_t b1f = *(uint32_t*)&Wts[(nt * 8 + r) * WPAD + kw + qc + 8];
                MMA16816(acc2[nt][0], acc2[nt][1], acc2[nt][2], acc2[nt][3],
                         a0, a1, a2, a3, b0, b1f);
            }
        }
    }

    // epilogue 2: * norm_src, fp16 store
    {
        int gr0 = row0 + m0 + r;
        int gr1 = gr0 + 8;
        float ns0 = (gr0 < n) ? g_norm_src[gr0] : 0.f;
        float ns1 = (gr1 < n) ? g_norm_src[gr1] : 0.f;
#pragma unroll
        for (int nt = 0; nt < 8; nt++) {
            int c = nt * 8 + qc;   // even
            if (gr0 < n)
                g_t_h[(size_t)gr0 * 32 + (c >> 1)] =
                    __floats2half2_rn(acc2[nt][0] * ns0, acc2[nt][1] * ns0);
            if (gr1 < n)
                g_t_h[(size_t)gr1 * 32 + (c >> 1)] =
                    __floats2half2_rn(acc2[nt][2] * ns1, acc2[nt][3] * ns1);
        }
    }
}

// ---------------- SpMM 2 (fp16 gather) ----------------
__global__ void k_spmm2(const float* __restrict__ b2, float* __restrict__ out, int n) {
    int w = (blockIdx.x * blockDim.x + threadIdx.x) >> 5;
    int lane = threadIdx.x & 31;
    if (w >= n) return;
    int beg = g_row_ptr[w];
    int end = g_row_ptr[w + 1];
    float2 acc = make_float2(0.f, 0.f);
    int ed = beg;
    for (; ed + 1 < end; ed += 2) {
        int s0 = g_csr_src[ed];
        int s1 = g_csr_src[ed + 1];
        float2 v0 = __half22float2(g_t_h[(size_t)s0 * 32 + lane]);
        float2 v1 = __half22float2(g_t_h[(size_t)s1 * 32 + lane]);
        acc.x += v0.x + v1.x;
        acc.y += v0.y + v1.y;
    }
    if (ed < end) {
        int s0 = g_csr_src[ed];
        float2 v0 = __half22float2(g_t_h[(size_t)s0 * 32 + lane]);
        acc.x += v0.x;
        acc.y += v0.y;
    }
    float nd = g_norm_dst[w];
    float2 bb = ((const float2*)b2)[lane];
    float2 o;
    o.x = fmaf(acc.x, nd, bb.x);
    o.y = fmaf(acc.y, nd, bb.y);
    ((float2*)out)[(size_t)w * 32 + lane] = o;
}

// ---------------- launch ----------------
extern "C" void kernel_launch(void* const* d_in, const int* in_sizes, int n_in,
                              void* d_out, int out_size) {
    const int* src = (const int*)d_in[1];
    const int* dst = (const int*)d_in[2];
    const float* emb = (const float*)d_in[3];
    const float* W1  = (const float*)d_in[4];
    const float* b1  = (const float*)d_in[5];
    const float* W2  = (const float*)d_in[6];
    const float* b2  = (const float*)d_in[7];
    float* out = (float*)d_out;

    const int n = in_sizes[0];
    const int e = in_sizes[1];

    k_zero<<<(n + 255) / 256, 256>>>(n);
    k_degree<<<(e + 255) / 256, 256>>>(src, dst, e);
    k_norm<<<(n + 255) / 256, 256>>>(n);
    k_prep<<<(n * 32 + 255) / 256, 256>>>(emb, n * 32);
    k_scan_partial<<<SCAN_NB, 256>>>(n);
    k_scan_blk<<<1, 128>>>(n, e);
    k_scan_final<<<SCAN_NB, 256>>>(n);
    k_fill<<<(e + 255) / 256, 256>>>(src, dst, e);

    int warps_grid = (n * 32 + 255) / 256;
    k_spmm1<<<warps_grid, 256>>>(n);
    k_gemm_mma<<<(n + 127) / 128, 256>>>(W1, b1, W2, n);
    k_spmm2<<<warps_grid, 256>>>(b2, out, n);
}

// round 8
// speedup vs baseline: 2.0404x; 1.0053x over previous
#include <cuda_runtime.h>
#include <cuda_fp16.h>
#include <cstdint>

#define NN 100000
#define NE 1600000
#define SCAN_TILE 1024
#define SCAN_NB ((NN + SCAN_TILE - 1) / SCAN_TILE)   // 98

#define APAD 136   // As row stride (halves)
#define WPAD 40    // Wts row stride (halves)

// m16n8k16 fp16 MMA, fp32 accumulate (sm_80+ PTX, works on compute_103)
#define MMA16816(c0, c1, c2, c3, a0, a1, a2, a3, b0, b1) \
    asm volatile("mma.sync.aligned.m16n8k16.row.col.f32.f16.f16.f32 " \
        "{%0,%1,%2,%3}, {%4,%5,%6,%7}, {%8,%9}, {%0,%1,%2,%3};" \
        : "+f"(c0), "+f"(c1), "+f"(c2), "+f"(c3) \
        : "r"(a0), "r"(a1), "r"(a2), "r"(a3), "r"(b0), "r"(b1))

// ---------------- device scratch ----------------
__device__ int     g_deg_in[NN];
__device__ int     g_deg_out[NN];
__device__ int     g_cursor[NN];
__device__ float   g_norm_src[NN];
__device__ float   g_norm_dst[NN];
__device__ int     g_row_ptr[NN + 1];
__device__ int     g_csr_src[NE];
__device__ int     g_blk_sum[SCAN_NB];
__device__ int     g_blk_off[SCAN_NB];
__device__ __half2 g_emb_h[(size_t)NN * 64];   // emb * norm_src, fp16
__device__ __half2 g_agg_h[(size_t)NN * 64];   // spmm1 result, fp16
__device__ __half2 g_t_h[(size_t)NN * 32];     // (h1@W2)*norm_src, fp16

// ---------------- setup ----------------
__global__ void k_zero(int n) {
    int i = blockIdx.x * blockDim.x + threadIdx.x;
    if (i < n) { g_deg_in[i] = 0; g_deg_out[i] = 0; g_cursor[i] = 0; }
}

// 2 edges per thread, int2 loads
__global__ void k_degree(const int* __restrict__ src,
                         const int* __restrict__ dst, int e2, int e) {
    int i = blockIdx.x * blockDim.x + threadIdx.x;
    if (i < e2) {
        int2 s = ((const int2*)src)[i];
        int2 d = ((const int2*)dst)[i];
        if ((unsigned)s.x < NN) atomicAdd(&g_deg_out[s.x], 1);
        if ((unsigned)s.y < NN) atomicAdd(&g_deg_out[s.y], 1);
        if ((unsigned)d.x < NN) atomicAdd(&g_deg_in[d.x], 1);
        if ((unsigned)d.y < NN) atomicAdd(&g_deg_in[d.y], 1);
    } else if (i == e2 && (e & 1)) {
        int s = src[e - 1], d = dst[e - 1];
        if ((unsigned)s < NN) atomicAdd(&g_deg_out[s], 1);
        if ((unsigned)d < NN) atomicAdd(&g_deg_in[d], 1);
    }
}

__global__ void k_norm(int n) {
    int i = blockIdx.x * blockDim.x + threadIdx.x;
    if (i < n) {
        int dout = g_deg_out[i]; if (dout < 1) dout = 1;
        int din  = g_deg_in[i];  if (din  < 1) din  = 1;
        g_norm_src[i] = rsqrtf((float)dout);
        g_norm_dst[i] = rsqrtf((float)din);
    }
}

// emb * norm_src -> half2; 8 floats per thread
__global__ void k_prep(const float* __restrict__ emb, int n16) {
    int i = blockIdx.x * blockDim.x + threadIdx.x;   // one per 8 feats
    if (i < n16) {
        int r = i >> 4;
        float4 v0 = ((const float4*)emb)[2 * i];
        float4 v1 = ((const float4*)emb)[2 * i + 1];
        float ns = g_norm_src[r];
        uint4 o;
        *(__half2*)&o.x = __floats2half2_rn(v0.x * ns, v0.y * ns);
        *(__half2*)&o.y = __floats2half2_rn(v0.z * ns, v0.w * ns);
        *(__half2*)&o.z = __floats2half2_rn(v1.x * ns, v1.y * ns);
        *(__half2*)&o.w = __floats2half2_rn(v1.z * ns, v1.w * ns);
        ((uint4*)g_emb_h)[i] = o;
    }
}

// ---------------- 3-phase exclusive scan ----------------
__global__ void __launch_bounds__(256)
k_scan_partial(int n) {
    __shared__ int sm[256];
    int t = threadIdx.x;
    int base = blockIdx.x * SCAN_TILE + t * 4;
    int s = 0;
#pragma unroll
    for (int j = 0; j < 4; j++) {
        int i = base + j;
        if (i < n) s += g_deg_in[i];
    }
    sm[t] = s;
    __syncthreads();
    for (int off = 128; off > 0; off >>= 1) {
        if (t < off) sm[t] += sm[t + off];
        __syncthreads();
    }
    if (t == 0) g_blk_sum[blockIdx.x] = sm[0];
}

__global__ void __launch_bounds__(128)
k_scan_blk(int n, int e) {
    __shared__ int sm[128];
    int t = threadIdx.x;
    int v = (t < SCAN_NB) ? g_blk_sum[t] : 0;
    sm[t] = v;
    __syncthreads();
    for (int off = 1; off < 128; off <<= 1) {
        int add = 0;
        if (t >= off) add = sm[t - off];
        __syncthreads();
        sm[t] += add;
        __syncthreads();
    }
    if (t < SCAN_NB) g_blk_off[t] = sm[t] - v;
    if (t == 0) g_row_ptr[n] = e;
}

__global__ void __launch_bounds__(256)
k_scan_final(int n) {
    __shared__ int sm[256];
    int t = threadIdx.x;
    int base = blockIdx.x * SCAN_TILE + t * 4;
    int d[4];
    int s = 0;
#pragma unroll
    for (int j = 0; j < 4; j++) {
        int i = base + j;
        d[j] = (i < n) ? g_deg_in[i] : 0;
        s += d[j];
    }
    sm[t] = s;
    __syncthreads();
    for (int off = 1; off < 256; off <<= 1) {
        int add = 0;
        if (t >= off) add = sm[t - off];
        __syncthreads();
        sm[t] += add;
        __syncthreads();
    }
    int run = g_blk_off[blockIdx.x] + sm[t] - s;
#pragma unroll
    for (int j = 0; j < 4; j++) {
        int i = base + j;
        if (i < n) g_row_ptr[i] = run;
        run += d[j];
    }
}

__global__ void k_fill(const int* __restrict__ src,
                       const int* __restrict__ dst, int e) {
    int i = blockIdx.x * blockDim.x + threadIdx.x;
    if (i < e) {
        int s = src[i];
        int d = dst[i];
        if ((unsigned)d < NN && (unsigned)s < NN) {
            int pos = g_row_ptr[d] + atomicAdd(&g_cursor[d], 1);
            g_csr_src[pos] = s;
        }
    }
}

// ---------------- SpMM 1 (fp16 gather, fp32 accumulate, fp16 out) ----------------
// warp per dst row, 4-edge unroll for MLP
__global__ void k_spmm1(int n) {
    int w = (blockIdx.x * blockDim.x + threadIdx.x) >> 5;
    int lane = threadIdx.x & 31;
    if (w >= n) return;
    int beg = g_row_ptr[w];
    int end = g_row_ptr[w + 1];
    const uint2* eh = (const uint2*)g_emb_h;   // row = 32 uint2
    float4 acc = make_float4(0.f, 0.f, 0.f, 0.f);
    int ed = beg;
    for (; ed + 3 < end; ed += 4) {
        int s0 = g_csr_src[ed];
        int s1 = g_csr_src[ed + 1];
        int s2 = g_csr_src[ed + 2];
        int s3 = g_csr_src[ed + 3];
        uint2 v0 = eh[(size_t)s0 * 32 + lane];
        uint2 v1 = eh[(size_t)s1 * 32 + lane];
        uint2 v2 = eh[(size_t)s2 * 32 + lane];
        uint2 v3 = eh[(size_t)s3 * 32 + lane];
        float2 a0 = __half22float2(*(__half2*)&v0.x), b0 = __half22float2(*(__half2*)&v0.y);
        float2 a1 = __half22float2(*(__half2*)&v1.x), b1 = __half22float2(*(__half2*)&v1.y);
        float2 a2 = __half22float2(*(__half2*)&v2.x), b2 = __half22float2(*(__half2*)&v2.y);
        float2 a3 = __half22float2(*(__half2*)&v3.x), b3 = __half22float2(*(__half2*)&v3.y);
        acc.x += (a0.x + a1.x) + (a2.x + a3.x);
        acc.y += (a0.y + a1.y) + (a2.y + a3.y);
        acc.z += (b0.x + b1.x) + (b2.x + b3.x);
        acc.w += (b0.y + b1.y) + (b2.y + b3.y);
    }
    for (; ed < end; ed++) {
        int s0 = g_csr_src[ed];
        uint2 v0 = eh[(size_t)s0 * 32 + lane];
        float2 a0 = __half22float2(*(__half2*)&v0.x);
        float2 b0 = __half22float2(*(__half2*)&v0.y);
        acc.x += a0.x; acc.y += a0.y; acc.z += b0.x; acc.w += b0.y;
    }
    float nd = g_norm_dst[w];
    uint2 o;
    *(__half2*)&o.x = __floats2half2_rn(acc.x * nd, acc.y * nd);
    *(__half2*)&o.y = __floats2half2_rn(acc.z * nd, acc.w * nd);
    ((uint2*)g_agg_h)[(size_t)w * 32 + lane] = o;
}

// ---------------- fused GEMM via HMMA (mma.sync m16n8k16) ----------------
__global__ void __launch_bounds__(256)
k_gemm_mma(const float* __restrict__ W1, const float* __restrict__ b1,
           const float* __restrict__ W2, int n) {
    __shared__ __half As[128 * APAD];    // 34.8KB
    __shared__ __half Wts[128 * WPAD];   // 10.2KB, [n][k] transposed chunks
    __shared__ float b1s[128];

    const int tid = threadIdx.x;
    const int lane = tid & 31;
    const int wid = tid >> 5;
    const int row0 = blockIdx.x * 128;
    const int m0 = wid * 16;
    const int r = lane >> 2;          // 0..7
    const int qc = (lane & 3) * 2;    // 0,2,4,6

    // load A tile (fp16, from g_agg_h), zero-pad OOB rows
    for (int i = tid; i < 128 * 32; i += 256) {
        int row = i >> 5, q = i & 31;
        int gr = row0 + row;
        uint2 v = make_uint2(0u, 0u);
        if (gr < n) v = ((const uint2*)g_agg_h)[(size_t)gr * 32 + q];
        *(uint2*)&As[row * APAD + q * 4] = v;
    }
    if (tid < 128) b1s[tid] = b1[tid];

    // ---- phase 1: 16x128 per warp, K=128 ----
    float acc[16][4];
#pragma unroll
    for (int t2 = 0; t2 < 16; t2++)
#pragma unroll
        for (int j = 0; j < 4; j++) acc[t2][j] = 0.f;

    for (int kc = 0; kc < 4; kc++) {
        __syncthreads();
        for (int i = tid; i < 32 * 128; i += 256) {
            int kl = i >> 7, nn = i & 127;
            Wts[nn * WPAD + kl] = __float2half(W1[(kc * 32 + kl) * 128 + nn]);
        }
        __syncthreads();
#pragma unroll
        for (int ks = 0; ks < 2; ks++) {
            int kb = kc * 32 + ks * 16;
            uint32_t a0 = *(uint32_t*)&As[(m0 + r) * APAD + kb + qc];
            uint32_t a1 = *(uint32_t*)&As[(m0 + r + 8) * APAD + kb + qc];
            uint32_t a2 = *(uint32_t*)&As[(m0 + r) * APAD + kb + qc + 8];
            uint32_t a3 = *(uint32_t*)&As[(m0 + r + 8) * APAD + kb + qc + 8];
            int kw = ks * 16;
#pragma unroll
            for (int nt = 0; nt < 16; nt++) {
                uint32_t b0 = *(uint32_t*)&Wts[(nt * 8 + r) * WPAD + kw + qc];
                uint32_t b1f = *(uint32_t*)&Wts[(nt * 8 + r) * WPAD + kw + qc + 8];
                MMA16816(acc[nt][0], acc[nt][1], acc[nt][2], acc[nt][3],
                         a0, a1, a2, a3, b0, b1f);
            }
        }
    }

    // epilogue 1: relu + bias, write h1 fp16 into As (own rows only)
#pragma unroll
    for (int nt = 0; nt < 16; nt++) {
        int c = nt * 8 + qc;
        float x0 = fmaxf(acc[nt][0] + b1s[c],     0.f);
        float x1 = fmaxf(acc[nt][1] + b1s[c + 1], 0.f);
        float x2 = fmaxf(acc[nt][2] + b1s[c],     0.f);
        float x3 = fmaxf(acc[nt][3] + b1s[c + 1], 0.f);
        *(__half2*)&As[(m0 + r) * APAD + c]     = __floats2half2_rn(x0, x1);
        *(__half2*)&As[(m0 + r + 8) * APAD + c] = __floats2half2_rn(x2, x3);
    }

    // ---- phase 2: 16x64 per warp, K=128 ----
    float acc2[8][4];
#pragma unroll
    for (int t2 = 0; t2 < 8; t2++)
#pragma unroll
        for (int j = 0; j < 4; j++) acc2[t2][j] = 0.f;

    for (int kc = 0; kc < 4; kc++) {
        __syncthreads();
        for (int i = tid; i < 32 * 64; i += 256) {
            int kl = i >> 6, nn = i & 63;
            Wts[nn * WPAD + kl] = __float2half(W2[(kc * 32 + kl) * 64 + nn]);
        }
        __syncthreads();
#pragma unroll
        for (int ks = 0; ks < 2; ks++) {
            int kb = kc * 32 + ks * 16;
            uint32_t a0 = *(uint32_t*)&As[(m0 + r) * APAD + kb + qc];
            uint32_t a1 = *(uint32_t*)&As[(m0 + r + 8) * APAD + kb + qc];
            uint32_t a2 = *(uint32_t*)&As[(m0 + r) * APAD + kb + qc + 8];
            uint32_t a3 = *(uint32_t*)&As[(m0 + r + 8) * APAD + kb + qc + 8];
            int kw = ks * 16;
#pragma unroll
            for (int nt = 0; nt < 8; nt++) {
                uint32_t b0 = *(uint32_t*)&Wts[(nt * 8 + r) * WPAD + kw + qc];
                uint32_t b1f = *(uint32_t*)&Wts[(nt * 8 + r) * WPAD + kw + qc + 8];
                MMA16816(acc2[nt][0], acc2[nt][1], acc2[nt][2], acc2[nt][3],
                         a0, a1, a2, a3, b0, b1f);
            }
        }
    }

    // epilogue 2: * norm_src, fp16 store
    {
        int gr0 = row0 + m0 + r;
        int gr1 = gr0 + 8;
        float ns0 = (gr0 < n) ? g_norm_src[gr0] : 0.f;
        float ns1 = (gr1 < n) ? g_norm_src[gr1] : 0.f;
#pragma unroll
        for (int nt = 0; nt < 8; nt++) {
            int c = nt * 8 + qc;   // even
            if (gr0 < n)
                g_t_h[(size_t)gr0 * 32 + (c >> 1)] =
                    __floats2half2_rn(acc2[nt][0] * ns0, acc2[nt][1] * ns0);
            if (gr1 < n)
                g_t_h[(size_t)gr1 * 32 + (c >> 1)] =
                    __floats2half2_rn(acc2[nt][2] * ns1, acc2[nt][3] * ns1);
        }
    }
}

// ---------------- SpMM 2 (fp16 gather, 4-edge unroll) ----------------
__global__ void k_spmm2(const float* __restrict__ b2, float* __restrict__ out, int n) {
    int w = (blockIdx.x * blockDim.x + threadIdx.x) >> 5;
    int lane = threadIdx.x & 31;
    if (w >= n) return;
    int beg = g_row_ptr[w];
    int end = g_row_ptr[w + 1];
    float2 acc = make_float2(0.f, 0.f);
    int ed = beg;
    for (; ed + 3 < end; ed += 4) {
        int s0 = g_csr_src[ed];
        int s1 = g_csr_src[ed + 1];
        int s2 = g_csr_src[ed + 2];
        int s3 = g_csr_src[ed + 3];
        float2 v0 = __half22float2(g_t_h[(size_t)s0 * 32 + lane]);
        float2 v1 = __half22float2(g_t_h[(size_t)s1 * 32 + lane]);
        float2 v2 = __half22float2(g_t_h[(size_t)s2 * 32 + lane]);
        float2 v3 = __half22float2(g_t_h[(size_t)s3 * 32 + lane]);
        acc.x += (v0.x + v1.x) + (v2.x + v3.x);
        acc.y += (v0.y + v1.y) + (v2.y + v3.y);
    }
    for (; ed < end; ed++) {
        int s0 = g_csr_src[ed];
        float2 v0 = __half22float2(g_t_h[(size_t)s0 * 32 + lane]);
        acc.x += v0.x;
        acc.y += v0.y;
    }
    float nd = g_norm_dst[w];
    float2 bb = ((const float2*)b2)[lane];
    float2 o;
    o.x = fmaf(acc.x, nd, bb.x);
    o.y = fmaf(acc.y, nd, bb.y);
    ((float2*)out)[(size_t)w * 32 + lane] = o;
}

// ---------------- launch ----------------
extern "C" void kernel_launch(void* const* d_in, const int* in_sizes, int n_in,
                              void* d_out, int out_size) {
    const int* src = (const int*)d_in[1];
    const int* dst = (const int*)d_in[2];
    const float* emb = (const float*)d_in[3];
    const float* W1  = (const float*)d_in[4];
    const float* b1  = (const float*)d_in[5];
    const float* W2  = (const float*)d_in[6];
    const float* b2  = (const float*)d_in[7];
    float* out = (float*)d_out;

    const int n = in_sizes[0];
    const int e = in_sizes[1];
    const int e2 = e >> 1;

    k_zero<<<(n + 255) / 256, 256>>>(n);
    k_degree<<<(e2 + 256) / 256, 256>>>(src, dst, e2, e);
    k_norm<<<(n + 255) / 256, 256>>>(n);
    k_prep<<<(n * 16 + 255) / 256, 256>>>(emb, n * 16);
    k_scan_partial<<<SCAN_NB, 256>>>(n);
    k_scan_blk<<<1, 128>>>(n, e);
    k_scan_final<<<SCAN_NB, 256>>>(n);
    k_fill<<<(e + 255) / 256, 256>>>(src, dst, e);

    int warps_grid = (n * 32 + 255) / 256;
    k_spmm1<<<warps_grid, 256>>>(n);
    k_gemm_mma<<<(n + 127) / 128, 256>>>(W1, b1, W2, n);
    k_spmm2<<<warps_grid, 256>>>(b2, out, n);
}